// round 4
// baseline (speedup 1.0000x reference)
#include <cuda_runtime.h>
#include <cuda_fp16.h>
#include <cuda_fp8.h>
#include <cuda.h>
#include <cstdint>

// ---------------------------------------------------------------------------
// Shapes (fixed): x[4,2048,4096] @ W[4096,4096]^T + bias -> out[8192,4096]
// ---------------------------------------------------------------------------
static constexpr int MM = 8192;
static constexpr int NN = 4096;
static constexpr int KK = 4096;
static constexpr int NG = KK / 32;          // 128 K-groups

static constexpr int TILE_M = 128;
static constexpr int TILE_N = 256;
static constexpr int KC     = 128;          // K elems per stage (128B fp8 rows)
static constexpr int DEPTH  = 3;
static constexpr int ITERS  = KK / KC;      // 32

static constexpr int A_ST   = TILE_M * KC;      // 16384 (fp8)
static constexpr int B_ST   = TILE_N * KC;      // 32768
static constexpr int AS_ST  = 4 * TILE_M * 4;   // 2048  (4 groups x 128 f32)
static constexpr int BS_ST  = 4 * TILE_N * 4;   // 4096
static constexpr int STAGE  = A_ST + B_ST + AS_ST + BS_ST;  // 55296

static constexpr int SM_STAGE0  = 1024;
static constexpr int SMEM_BYTES = SM_STAGE0 + DEPTH * STAGE;  // 166912

// ---------------------------------------------------------------------------
// Scratch: fp8 quantized operands + per-group scales (transposed [g][row])
// ---------------------------------------------------------------------------
__device__ __align__(1024) uint8_t g_xq8[(size_t)MM * KK];   // 32 MB
__device__ __align__(1024) uint8_t g_wq8[(size_t)NN * KK];   // 16 MB
__device__ __align__(1024) float   g_xs[(size_t)NG * MM];    // 4 MB
__device__ __align__(1024) float   g_ws[(size_t)NG * NN];    // 2 MB

// ---------------------------------------------------------------------------
// PTX helpers
// ---------------------------------------------------------------------------
__device__ __forceinline__ uint32_t smem_u32(const void* p) {
    uint32_t a;
    asm("{ .reg .u64 t; cvta.to.shared.u64 t, %1; cvt.u32.u64 %0, t; }" : "=r"(a) : "l"(p));
    return a;
}
__device__ __forceinline__ void mbar_init(uint32_t a, uint32_t cnt) {
    asm volatile("mbarrier.init.shared.b64 [%0], %1;" :: "r"(a), "r"(cnt) : "memory");
}
__device__ __forceinline__ void mbar_expect_tx(uint32_t a, uint32_t bytes) {
    asm volatile("mbarrier.arrive.expect_tx.shared.b64 _, [%0], %1;" :: "r"(a), "r"(bytes) : "memory");
}
__device__ __forceinline__ void mbar_wait(uint32_t a, uint32_t ph) {
    asm volatile(
        "{\n\t.reg .pred P;\n"
        "LW_%=:\n\t"
        "mbarrier.try_wait.parity.acquire.cta.shared::cta.b64 P, [%0], %1, 0x989680;\n\t"
        "@P bra LD_%=;\n\t"
        "bra LW_%=;\n"
        "LD_%=:\n\t}"
        :: "r"(a), "r"(ph) : "memory");
}
__device__ __forceinline__ void tma2d(uint32_t dst, const CUtensorMap* m, int cx, int cy, uint32_t bar) {
    asm volatile(
        "cp.async.bulk.tensor.2d.shared::cta.global.tile.mbarrier::complete_tx::bytes "
        "[%0], [%1, {%2, %3}], [%4];"
        :: "r"(dst), "l"(m), "r"(cx), "r"(cy), "r"(bar) : "memory");
}
__device__ __forceinline__ void fence_proxy_async_s() {
    asm volatile("fence.proxy.async.shared::cta;" ::: "memory");
}
__device__ __forceinline__ void ldsm_x4(uint32_t* r, uint32_t addr) {
    asm volatile("ldmatrix.sync.aligned.m8n8.x4.shared.b16 {%0,%1,%2,%3}, [%4];"
                 : "=r"(r[0]), "=r"(r[1]), "=r"(r[2]), "=r"(r[3]) : "r"(addr));
}
// fp8 e4m3 MMA, C = 0 (fresh group partial)
__device__ __forceinline__ void mma_e4m3(float* d, const uint32_t* a, const uint32_t* b) {
    asm volatile(
        "mma.sync.aligned.m16n8k32.row.col.f32.e4m3.e4m3.f32 "
        "{%0,%1,%2,%3}, {%4,%5,%6,%7}, {%8,%9}, {%10,%10,%10,%10};"
        : "=f"(d[0]), "=f"(d[1]), "=f"(d[2]), "=f"(d[3])
        : "r"(a[0]), "r"(a[1]), "r"(a[2]), "r"(a[3]), "r"(b[0]), "r"(b[1]), "f"(0.0f));
}
// packed f32x2 (Blackwell)
__device__ __forceinline__ uint64_t pack2(float lo, float hi) {
    uint64_t r; asm("mov.b64 %0, {%1, %2};" : "=l"(r) : "f"(lo), "f"(hi)); return r;
}
__device__ __forceinline__ void unpack2(float& lo, float& hi, uint64_t v) {
    asm("mov.b64 {%0, %1}, %2;" : "=f"(lo), "=f"(hi) : "l"(v));
}
__device__ __forceinline__ uint64_t mul2(uint64_t a, uint64_t b) {
    uint64_t d; asm("mul.rn.f32x2 %0, %1, %2;" : "=l"(d) : "l"(a), "l"(b)); return d;
}
__device__ __forceinline__ uint64_t fma2(uint64_t a, uint64_t b, uint64_t c) {
    uint64_t d; asm("fma.rn.f32x2 %0, %1, %2, %3;" : "=l"(d) : "l"(a), "l"(b), "l"(c)); return d;
}
__device__ __forceinline__ float lds_f32(uint32_t a) {
    float v; asm volatile("ld.shared.f32 %0, [%1];" : "=f"(v) : "r"(a)); return v;
}
__device__ __forceinline__ uint64_t lds_b64(uint32_t a) {
    uint64_t v; asm volatile("ld.shared.b64 %0, [%1];" : "=l"(v) : "r"(a)); return v;
}

// ---------------------------------------------------------------------------
// Kernel 1: fp8-e4m3 group(32) quantize -> q (fp8) + transposed scales [g][row]
// thread = 4 consecutive elems; group = 8 consecutive lanes
// ---------------------------------------------------------------------------
__global__ void __launch_bounds__(256) quant8_kernel(const float* __restrict__ src,
                                                     uint8_t* __restrict__ q,
                                                     float* __restrict__ s_t,
                                                     int rows, int n4) {
    int t = blockIdx.x * 256 + threadIdx.x;
    if (t >= n4) return;
    float4 v = reinterpret_cast<const float4*>(src)[t];
    float amax = fmaxf(fmaxf(fabsf(v.x), fabsf(v.y)), fmaxf(fabsf(v.z), fabsf(v.w)));
    amax = fmaxf(amax, __shfl_xor_sync(0xffffffffu, amax, 1));
    amax = fmaxf(amax, __shfl_xor_sync(0xffffffffu, amax, 2));
    amax = fmaxf(amax, __shfl_xor_sync(0xffffffffu, amax, 4));
    float scale = __fdiv_rn(fmaxf(amax, 1e-8f), 448.0f);
    float inv = __frcp_rn(scale);   // NOT used for quant math; only scale div below
    (void)inv;

    uint32_t pk = 0;
    pk |= (uint32_t)__nv_cvt_float_to_fp8(__fdiv_rn(v.x, scale), __NV_SATFINITE, __NV_E4M3);
    pk |= (uint32_t)__nv_cvt_float_to_fp8(__fdiv_rn(v.y, scale), __NV_SATFINITE, __NV_E4M3) << 8;
    pk |= (uint32_t)__nv_cvt_float_to_fp8(__fdiv_rn(v.z, scale), __NV_SATFINITE, __NV_E4M3) << 16;
    pk |= (uint32_t)__nv_cvt_float_to_fp8(__fdiv_rn(v.w, scale), __NV_SATFINITE, __NV_E4M3) << 24;
    reinterpret_cast<uint32_t*>(q)[t] = pk;

    if ((threadIdx.x & 7) == 0) {
        int e0  = t * 4;
        int row = e0 >> 12;          // / KK (4096)
        int g   = (e0 & (KK - 1)) >> 5;
        s_t[(size_t)g * rows + row] = scale;
    }
}

// ---------------------------------------------------------------------------
// Kernel 2: fp8 mma.sync GEMM with exact per-group rescale
// 256 threads = 8 warps, warp grid 2(M) x 4(N), warp tile 64x64
// ---------------------------------------------------------------------------
__global__ void __launch_bounds__(256, 1) gemm_fp8_kernel(
    const __grid_constant__ CUtensorMap tma_a,
    const __grid_constant__ CUtensorMap tma_b,
    const __grid_constant__ CUtensorMap tma_as,
    const __grid_constant__ CUtensorMap tma_bs,
    const float* __restrict__ bias,
    float* __restrict__ out) {
    extern __shared__ char smem[];
    const uint32_t sb = smem_u32(smem);
    const int tid  = threadIdx.x;
    const int lane = tid & 31;
    const int wid  = tid >> 5;
    const int wm   = wid & 1;
    const int wn   = wid >> 1;

    const int TILES_N = NN / TILE_N;              // 16
    const int TIG = 8 * TILES_N;                  // 128
    int bid = blockIdx.x;
    int grp = bid / TIG, rem = bid % TIG;
    const int m0 = (grp * 8 + (rem & 7)) * TILE_M;
    const int n0 = (rem >> 3) * TILE_N;

    if (tid == 0) {
        #pragma unroll
        for (int s = 0; s < DEPTH; s++) mbar_init(sb + 8 * s, 1);
        fence_proxy_async_s();
    }
    __syncthreads();

    const CUtensorMap* pa  = &tma_a;
    const CUtensorMap* pb  = &tma_b;
    const CUtensorMap* pas = &tma_as;
    const CUtensorMap* pbs = &tma_bs;
    if (tid == 0) {
        asm volatile("prefetch.tensormap [%0];" :: "l"(pa));
        asm volatile("prefetch.tensormap [%0];" :: "l"(pb));
        asm volatile("prefetch.tensormap [%0];" :: "l"(pas));
        asm volatile("prefetch.tensormap [%0];" :: "l"(pbs));
        #pragma unroll
        for (int s = 0; s < DEPTH - 1; s++) {
            mbar_expect_tx(sb + 8 * s, STAGE);
            uint32_t dst = sb + SM_STAGE0 + s * STAGE;
            tma2d(dst, pa, s * KC, m0, sb + 8 * s);
            tma2d(dst + A_ST, pb, s * KC, n0, sb + 8 * s);
            tma2d(dst + A_ST + B_ST, pas, m0, s * 4, sb + 8 * s);
            tma2d(dst + A_ST + B_ST + AS_ST, pbs, n0, s * 4, sb + 8 * s);
        }
    }

    // ldmatrix swizzled base offsets (byte-identical to fp16 case: 128B rows)
    uint32_t aR[4], aSX[4];
    const uint32_t aQ = ((lane >> 4) & 1) * 16;
    #pragma unroll
    for (int mi = 0; mi < 4; mi++) {
        uint32_t row = wm * 64 + mi * 16 + (lane & 15);
        aR[mi]  = row * 128;
        aSX[mi] = (aR[mi] >> 3) & 0x70;
    }
    uint32_t bR[4], bSX[4];
    const uint32_t bQ = ((lane >> 3) & 1) * 16;
    #pragma unroll
    for (int j = 0; j < 4; j++) {
        uint32_t row = wn * 64 + j * 16 + (lane & 7) + ((lane >> 4) & 1) * 8;
        bR[j]  = row * 128;
        bSX[j] = (bR[j] >> 3) & 0x70;
    }

    // scale lane offsets
    const uint32_t saOffLo = (uint32_t)(wm * 64 + (lane >> 2)) * 4;   // + mi*64B
    const uint32_t sbOff   = (uint32_t)(wn * 64 + 2 * (lane & 3)) * 4; // + nj*32B

    uint64_t c01[4][8], c23[4][8];
    #pragma unroll
    for (int mi = 0; mi < 4; mi++)
        #pragma unroll
        for (int nj = 0; nj < 8; nj++) { c01[mi][nj] = 0ull; c23[mi][nj] = 0ull; }

    for (int it = 0; it < ITERS; ++it) {
        int s = it % DEPTH;
        if (tid == 0 && it + DEPTH - 1 < ITERS) {
            int blk = it + DEPTH - 1, ss = blk % DEPTH;
            mbar_expect_tx(sb + 8 * ss, STAGE);
            uint32_t dst = sb + SM_STAGE0 + ss * STAGE;
            tma2d(dst, pa, blk * KC, m0, sb + 8 * ss);
            tma2d(dst + A_ST, pb, blk * KC, n0, sb + 8 * ss);
            tma2d(dst + A_ST + B_ST, pas, m0, blk * 4, sb + 8 * ss);
            tma2d(dst + A_ST + B_ST + AS_ST, pbs, n0, blk * 4, sb + 8 * ss);
        }
        mbar_wait(sb + 8 * s, (uint32_t)((it / DEPTH) & 1));

        const uint32_t aS  = sb + SM_STAGE0 + s * STAGE;
        const uint32_t bS  = aS + A_ST;
        const uint32_t asS = bS + B_ST;
        const uint32_t bsS = asS + AS_ST;

        #pragma unroll
        for (int g = 0; g < 4; ++g) {           // one K-group of 32 per mma
            uint32_t a[4][4], b[4][4];
            const uint32_t ck = (uint32_t)(g * 32);
            #pragma unroll
            for (int mi = 0; mi < 4; mi++)
                ldsm_x4(a[mi], aS + aR[mi] + ((ck | aQ) ^ aSX[mi]));
            #pragma unroll
            for (int j = 0; j < 4; j++)
                ldsm_x4(b[j], bS + bR[j] + ((ck | bQ) ^ bSX[j]));

            uint64_t sa_lo[4], sa_hi[4];
            #pragma unroll
            for (int mi = 0; mi < 4; mi++) {
                float lo = lds_f32(asS + g * 512 + saOffLo + mi * 64);
                float hi = lds_f32(asS + g * 512 + saOffLo + mi * 64 + 32);
                sa_lo[mi] = pack2(lo, lo);
                sa_hi[mi] = pack2(hi, hi);
            }
            uint64_t p[8];
            #pragma unroll
            for (int nj = 0; nj < 8; nj++)
                p[nj] = lds_b64(bsS + g * 1024 + sbOff + nj * 32);

            #pragma unroll
            for (int mi = 0; mi < 4; mi++) {
                #pragma unroll
                for (int nj = 0; nj < 8; nj++) {
                    float t[4];
                    mma_e4m3(t, a[mi], &b[nj >> 1][(nj & 1) * 2]);
                    uint64_t t01 = pack2(t[0], t[1]);
                    uint64_t t23 = pack2(t[2], t[3]);
                    c01[mi][nj] = fma2(t01, mul2(sa_lo[mi], p[nj]), c01[mi][nj]);
                    c23[mi][nj] = fma2(t23, mul2(sa_hi[mi], p[nj]), c23[mi][nj]);
                }
            }
        }
        __syncthreads();
    }

    // epilogue: bias + float2 stores
    const int cbase = n0 + wn * 64 + (lane & 3) * 2;
    #pragma unroll
    for (int nj = 0; nj < 8; nj++) {
        const int col = cbase + nj * 8;
        const float2 bv = *reinterpret_cast<const float2*>(&bias[col]);
        #pragma unroll
        for (int mi = 0; mi < 4; mi++) {
            const int row = m0 + wm * 64 + mi * 16 + (lane >> 2);
            float l0, h0, l1, h1;
            unpack2(l0, h0, c01[mi][nj]);
            unpack2(l1, h1, c23[mi][nj]);
            float2 v0 = {l0 + bv.x, h0 + bv.y};
            float2 v1 = {l1 + bv.x, h1 + bv.y};
            *reinterpret_cast<float2*>(&out[(size_t)row * NN + col])       = v0;
            *reinterpret_cast<float2*>(&out[(size_t)(row + 8) * NN + col]) = v1;
        }
    }
}

// ---------------------------------------------------------------------------
// Host launcher
// ---------------------------------------------------------------------------
typedef CUresult (*PFN_encodeTiled)(CUtensorMap*, CUtensorMapDataType, cuuint32_t, void*,
                                    const cuuint64_t*, const cuuint64_t*, const cuuint32_t*,
                                    const cuuint32_t*, CUtensorMapInterleave, CUtensorMapSwizzle,
                                    CUtensorMapL2promotion, CUtensorMapFloatOOBfill);

static bool enc2d(PFN_encodeTiled enc, CUtensorMap* m, void* p, CUtensorMapDataType dt,
                  long long d0, long long d1, long long strideB,
                  int b0, int b1, CUtensorMapSwizzle sw) {
    cuuint64_t dims[2]    = {(cuuint64_t)d0, (cuuint64_t)d1};
    cuuint64_t strides[1] = {(cuuint64_t)strideB};
    cuuint32_t box[2]     = {(cuuint32_t)b0, (cuuint32_t)b1};
    cuuint32_t es[2]      = {1, 1};
    return enc(m, dt, 2, p, dims, strides, box, es,
               CU_TENSOR_MAP_INTERLEAVE_NONE, sw,
               CU_TENSOR_MAP_L2_PROMOTION_L2_128B,
               CU_TENSOR_MAP_FLOAT_OOB_FILL_NONE) == CUDA_SUCCESS;
}

extern "C" void kernel_launch(void* const* d_in, const int* in_sizes, int n_in,
                              void* d_out, int out_size) {
    if (n_in < 3) return;
    const float* x    = (const float*)d_in[0];
    const float* W    = (const float*)d_in[1];
    const float* bias = (const float*)d_in[2];
    float* out = (float*)d_out;

    void *pA = nullptr, *pB = nullptr, *pAS = nullptr, *pBS = nullptr;
    cudaGetSymbolAddress(&pA, g_xq8);
    cudaGetSymbolAddress(&pB, g_wq8);
    cudaGetSymbolAddress(&pAS, g_xs);
    cudaGetSymbolAddress(&pBS, g_ws);

    // 1) fp8 quantize -> q + transposed scales
    {
        int n4x = (int)(((long long)MM * KK) / 4);
        int n4w = (int)(((long long)NN * KK) / 4);
        quant8_kernel<<<(n4x + 255) / 256, 256>>>(x, (uint8_t*)pA, (float*)pAS, MM, n4x);
        quant8_kernel<<<(n4w + 255) / 256, 256>>>(W, (uint8_t*)pB, (float*)pBS, NN, n4w);
    }

    // 2) TMA descriptors
    void* fn = nullptr;
    cudaDriverEntryPointQueryResult qr;
    cudaGetDriverEntryPointByVersion("cuTensorMapEncodeTiled", &fn, 12000,
                                     cudaEnableDefault, &qr);
    if (!fn) return;
    PFN_encodeTiled enc = (PFN_encodeTiled)fn;

    CUtensorMap ma, mb, mas, mbs;
    if (!enc2d(enc, &ma, pA, CU_TENSOR_MAP_DATA_TYPE_UINT8, KK, MM, KK,
               KC, TILE_M, CU_TENSOR_MAP_SWIZZLE_128B)) return;
    if (!enc2d(enc, &mb, pB, CU_TENSOR_MAP_DATA_TYPE_UINT8, KK, NN, KK,
               KC, TILE_N, CU_TENSOR_MAP_SWIZZLE_128B)) return;
    if (!enc2d(enc, &mas, pAS, CU_TENSOR_MAP_DATA_TYPE_FLOAT32, MM, NG, (long long)MM * 4,
               TILE_M, 4, CU_TENSOR_MAP_SWIZZLE_NONE)) return;
    if (!enc2d(enc, &mbs, pBS, CU_TENSOR_MAP_DATA_TYPE_FLOAT32, NN, NG, (long long)NN * 4,
               TILE_N, 4, CU_TENSOR_MAP_SWIZZLE_NONE)) return;

    // 3) GEMM
    cudaFuncSetAttribute(gemm_fp8_kernel, cudaFuncAttributeMaxDynamicSharedMemorySize,
                         SMEM_BYTES);
    int grid = (MM / TILE_M) * (NN / TILE_N);   // 1024
    gemm_fp8_kernel<<<grid, 256, SMEM_BYTES>>>(ma, mb, mas, mbs, bias, out);
    (void)in_sizes; (void)out_size;
}

// round 5
// speedup vs baseline: 1.8858x; 1.8858x over previous
#include <cuda_runtime.h>
#include <cuda_fp16.h>
#include <cuda_fp8.h>
#include <cuda.h>
#include <cstdint>

// ---------------------------------------------------------------------------
// Shapes (fixed): x[4,2048,4096] @ W[4096,4096]^T + bias -> out[8192,4096]
// ---------------------------------------------------------------------------
static constexpr int MM = 8192;
static constexpr int NN = 4096;
static constexpr int KK = 4096;

static constexpr int TILE_M = 128;
static constexpr int TILE_N = 256;
static constexpr int KC     = 64;          // K per stage (128B rows, SW128)
static constexpr int DEPTH  = 4;
static constexpr int ITERS  = KK / KC;     // 64

static constexpr int A_ST  = TILE_M * KC * 2;   // 16384
static constexpr int B_ST  = TILE_N * KC * 2;   // 32768
static constexpr int STAGE = A_ST + B_ST;       // 49152

static constexpr int SM_STAGE0  = 1024;         // 1024-aligned for SW128
static constexpr int SMEM_BYTES = SM_STAGE0 + DEPTH * STAGE;   // 197632

// ---------------------------------------------------------------------------
// Scratch: dequantized fp16 operands (device globals per harness rules)
// ---------------------------------------------------------------------------
__device__ __align__(1024) __half g_xq[(size_t)MM * KK];   // 64 MB
__device__ __align__(1024) __half g_wq[(size_t)NN * KK];   // 32 MB

// ---------------------------------------------------------------------------
// PTX helpers (family-portable only: TMA, mbarrier, ldmatrix, mma.sync)
// ---------------------------------------------------------------------------
__device__ __forceinline__ uint32_t smem_u32(const void* p) {
    uint32_t a;
    asm("{ .reg .u64 t; cvta.to.shared.u64 t, %1; cvt.u32.u64 %0, t; }" : "=r"(a) : "l"(p));
    return a;
}
__device__ __forceinline__ void mbar_init(uint32_t a, uint32_t cnt) {
    asm volatile("mbarrier.init.shared.b64 [%0], %1;" :: "r"(a), "r"(cnt) : "memory");
}
__device__ __forceinline__ void mbar_expect_tx(uint32_t a, uint32_t bytes) {
    asm volatile("mbarrier.arrive.expect_tx.shared.b64 _, [%0], %1;" :: "r"(a), "r"(bytes) : "memory");
}
__device__ __forceinline__ void mbar_arrive(uint32_t a) {
    asm volatile("mbarrier.arrive.shared.b64 _, [%0];" :: "r"(a) : "memory");
}
__device__ __forceinline__ void mbar_wait(uint32_t a, uint32_t ph) {
    asm volatile(
        "{\n\t.reg .pred P;\n"
        "LW_%=:\n\t"
        "mbarrier.try_wait.parity.acquire.cta.shared::cta.b64 P, [%0], %1, 0x989680;\n\t"
        "@P bra LD_%=;\n\t"
        "bra LW_%=;\n"
        "LD_%=:\n\t}"
        :: "r"(a), "r"(ph) : "memory");
}
__device__ __forceinline__ void mbar_wait_relaxed(uint32_t a, uint32_t ph) {
    asm volatile(
        "{\n\t.reg .pred P;\n"
        "LW_%=:\n\t"
        "mbarrier.try_wait.parity.relaxed.cta.shared::cta.b64 P, [%0], %1, 0x989680;\n\t"
        "@P bra LD_%=;\n\t"
        "bra LW_%=;\n"
        "LD_%=:\n\t}"
        :: "r"(a), "r"(ph) : "memory");
}
__device__ __forceinline__ void tma2d(uint32_t dst, const CUtensorMap* m, int cx, int cy, uint32_t bar) {
    asm volatile(
        "cp.async.bulk.tensor.2d.shared::cta.global.tile.mbarrier::complete_tx::bytes "
        "[%0], [%1, {%2, %3}], [%4];"
        :: "r"(dst), "l"(m), "r"(cx), "r"(cy), "r"(bar) : "memory");
}
__device__ __forceinline__ void fence_proxy_async_s() {
    asm volatile("fence.proxy.async.shared::cta;" ::: "memory");
}
__device__ __forceinline__ void ldsm_x4(uint32_t* r, uint32_t addr) {
    asm volatile("ldmatrix.sync.aligned.m8n8.x4.shared.b16 {%0,%1,%2,%3}, [%4];"
                 : "=r"(r[0]), "=r"(r[1]), "=r"(r[2]), "=r"(r[3]) : "r"(addr));
}
__device__ __forceinline__ void mma16816(float* c, const uint32_t* a, const uint32_t* b) {
    asm volatile(
        "mma.sync.aligned.m16n8k16.row.col.f32.f16.f16.f32 "
        "{%0,%1,%2,%3}, {%4,%5,%6,%7}, {%8,%9}, {%0,%1,%2,%3};"
        : "+f"(c[0]), "+f"(c[1]), "+f"(c[2]), "+f"(c[3])
        : "r"(a[0]), "r"(a[1]), "r"(a[2]), "r"(a[3]), "r"(b[0]), "r"(b[1]));
}

// ---------------------------------------------------------------------------
// Kernel 1: fp8-e4m3 group(32) pseudo-quantize -> dequantize to fp16 scratch
// ---------------------------------------------------------------------------
__device__ __forceinline__ float f8_roundtrip(float x, float scale) {
    float r = __fdiv_rn(x, scale);
    __nv_fp8_storage_t q = __nv_cvt_float_to_fp8(r, __NV_SATFINITE, __NV_E4M3);
    __half_raw hr = __nv_cvt_fp8_to_halfraw(q, __NV_E4M3);
    return __half2float(__half(hr)) * scale;
}

__global__ void __launch_bounds__(256) quant_deq_kernel(const float* __restrict__ src,
                                                        __half* __restrict__ dst, int n4) {
    int t = blockIdx.x * 256 + threadIdx.x;
    if (t >= n4) return;
    float4 v = reinterpret_cast<const float4*>(src)[t];
    float amax = fmaxf(fmaxf(fabsf(v.x), fabsf(v.y)), fmaxf(fabsf(v.z), fabsf(v.w)));
    amax = fmaxf(amax, __shfl_xor_sync(0xffffffffu, amax, 1));
    amax = fmaxf(amax, __shfl_xor_sync(0xffffffffu, amax, 2));
    amax = fmaxf(amax, __shfl_xor_sync(0xffffffffu, amax, 4));
    float scale = __fdiv_rn(fmaxf(amax, 1e-8f), 448.0f);

    __half2 h01 = __halves2half2(__float2half_rn(f8_roundtrip(v.x, scale)),
                                 __float2half_rn(f8_roundtrip(v.y, scale)));
    __half2 h23 = __halves2half2(__float2half_rn(f8_roundtrip(v.z, scale)),
                                 __float2half_rn(f8_roundtrip(v.w, scale)));
    __half2* d2 = reinterpret_cast<__half2*>(dst) + (size_t)t * 2;
    d2[0] = h01;
    d2[1] = h23;
}

// ---------------------------------------------------------------------------
// Kernel 2: mma.sync fp16 GEMM  out[M,N] = A[M,K] @ B[N,K]^T + bias
// 256 threads = 8 warps, warp grid 2(M) x 4(N), warp tile 64x64
// TMA multistage (DEPTH=4) with full/empty mbarrier pairs (no __syncthreads
// in the mainloop — warps decouple, producer gated on true buffer reuse)
// ---------------------------------------------------------------------------
__global__ void __launch_bounds__(256, 1) gemm_hmma_kernel(
    const __grid_constant__ CUtensorMap tma_a,
    const __grid_constant__ CUtensorMap tma_b,
    const float* __restrict__ bias,
    float* __restrict__ out) {
    extern __shared__ char smem[];
    const uint32_t sb = smem_u32(smem);
    const int tid  = threadIdx.x;
    const int lane = tid & 31;
    const int wid  = tid >> 5;
    const int wm   = wid & 1;    // 0..1 (64-row half)
    const int wn   = wid >> 1;   // 0..3 (64-col quarter)

    // Grid swizzle: groups of 8 M-tiles, N fastest (L2 locality)
    const int TILES_N = NN / TILE_N;              // 16
    const int TIG = 8 * TILES_N;                  // 128
    int bid = blockIdx.x;
    int grp = bid / TIG, rem = bid % TIG;
    const int m0 = (grp * 8 + (rem & 7)) * TILE_M;
    const int n0 = (rem >> 3) * TILE_N;

    // barriers: full[s] @ sb+16s, empty[s] @ sb+16s+8
    if (tid == 0) {
        #pragma unroll
        for (int s = 0; s < DEPTH; s++) {
            mbar_init(sb + 16 * s, 1);       // full: 1 arrive (expect_tx) + tx
            mbar_init(sb + 16 * s + 8, 8);   // empty: one arrive per warp
        }
        fence_proxy_async_s();
    }
    __syncthreads();

    const CUtensorMap* pa = &tma_a;
    const CUtensorMap* pb = &tma_b;
    if (tid == 0) {
        asm volatile("prefetch.tensormap [%0];" :: "l"(pa));
        asm volatile("prefetch.tensormap [%0];" :: "l"(pb));
        #pragma unroll
        for (int s = 0; s < DEPTH - 1; s++) {
            mbar_expect_tx(sb + 16 * s, STAGE);
            uint32_t dst = sb + SM_STAGE0 + s * STAGE;
            tma2d(dst, pa, s * KC, m0, sb + 16 * s);
            tma2d(dst + A_ST, pb, s * KC, n0, sb + 16 * s);
        }
    }

    // ---- per-thread swizzled ldmatrix base offsets ----
    uint32_t aR[4], aSX[4];
    const uint32_t aQ = ((lane >> 4) & 1) * 16;
    #pragma unroll
    for (int mi = 0; mi < 4; mi++) {
        uint32_t row = wm * 64 + mi * 16 + (lane & 15);
        aR[mi]  = row * 128;
        aSX[mi] = (aR[mi] >> 3) & 0x70;
    }
    uint32_t bR[4], bSX[4];
    const uint32_t bQ = ((lane >> 3) & 1) * 16;
    #pragma unroll
    for (int j = 0; j < 4; j++) {
        uint32_t row = wn * 64 + j * 16 + (lane & 7) + ((lane >> 4) & 1) * 8;
        bR[j]  = row * 128;
        bSX[j] = (bR[j] >> 3) & 0x70;
    }

    float c[4][8][4];
    #pragma unroll
    for (int mi = 0; mi < 4; mi++)
        #pragma unroll
        for (int nj = 0; nj < 8; nj++)
            #pragma unroll
            for (int k = 0; k < 4; k++) c[mi][nj][k] = 0.f;

    // ---- main loop (no CTA-wide sync) ----
    for (int it = 0; it < ITERS; ++it) {
        int s = it % DEPTH;
        if (tid == 0 && it + DEPTH - 1 < ITERS) {
            int blk = it + DEPTH - 1, ss = blk % DEPTH;
            int v = blk / DEPTH;                 // reuse count of stage ss
            if (v >= 1)
                mbar_wait_relaxed(sb + 16 * ss + 8, (uint32_t)((v - 1) & 1));
            mbar_expect_tx(sb + 16 * ss, STAGE);
            uint32_t dst = sb + SM_STAGE0 + ss * STAGE;
            tma2d(dst, pa, blk * KC, m0, sb + 16 * ss);
            tma2d(dst + A_ST, pb, blk * KC, n0, sb + 16 * ss);
        }
        mbar_wait(sb + 16 * s, (uint32_t)((it / DEPTH) & 1));

        const uint32_t aS = sb + SM_STAGE0 + s * STAGE;
        const uint32_t bS = aS + A_ST;
        #pragma unroll
        for (int kk = 0; kk < KC / 16; ++kk) {
            uint32_t a[4][4], b[4][4];
            const uint32_t ck = (uint32_t)(kk * 32);
            #pragma unroll
            for (int mi = 0; mi < 4; mi++)
                ldsm_x4(a[mi], aS + aR[mi] + ((ck | aQ) ^ aSX[mi]));
            #pragma unroll
            for (int j = 0; j < 4; j++)
                ldsm_x4(b[j], bS + bR[j] + ((ck | bQ) ^ bSX[j]));
            #pragma unroll
            for (int mi = 0; mi < 4; mi++)
                #pragma unroll
                for (int nj = 0; nj < 8; nj++)
                    mma16816(c[mi][nj], a[mi], &b[nj >> 1][(nj & 1) * 2]);
        }
        // all smem reads from this stage are complete (ldmatrix is synchronous)
        if (lane == 0) mbar_arrive(sb + 16 * s + 8);
    }

    // ---- epilogue: bias + direct float2 stores ----
    const int cbase = n0 + wn * 64 + (lane & 3) * 2;
    #pragma unroll
    for (int nj = 0; nj < 8; nj++) {
        const int col = cbase + nj * 8;
        const float2 bv = *reinterpret_cast<const float2*>(&bias[col]);
        #pragma unroll
        for (int mi = 0; mi < 4; mi++) {
            const int row = m0 + wm * 64 + mi * 16 + (lane >> 2);
            float2 v0 = {c[mi][nj][0] + bv.x, c[mi][nj][1] + bv.y};
            float2 v1 = {c[mi][nj][2] + bv.x, c[mi][nj][3] + bv.y};
            *reinterpret_cast<float2*>(&out[(size_t)row * NN + col])       = v0;
            *reinterpret_cast<float2*>(&out[(size_t)(row + 8) * NN + col]) = v1;
        }
    }
}

// ---------------------------------------------------------------------------
// Host launcher
// ---------------------------------------------------------------------------
typedef CUresult (*PFN_encodeTiled)(CUtensorMap*, CUtensorMapDataType, cuuint32_t, void*,
                                    const cuuint64_t*, const cuuint64_t*, const cuuint32_t*,
                                    const cuuint32_t*, CUtensorMapInterleave, CUtensorMapSwizzle,
                                    CUtensorMapL2promotion, CUtensorMapFloatOOBfill);

extern "C" void kernel_launch(void* const* d_in, const int* in_sizes, int n_in,
                              void* d_out, int out_size) {
    if (n_in < 3) return;
    const float* x    = (const float*)d_in[0];
    const float* W    = (const float*)d_in[1];
    const float* bias = (const float*)d_in[2];
    float* out = (float*)d_out;

    void* pA = nullptr;
    void* pB = nullptr;
    cudaGetSymbolAddress(&pA, g_xq);
    cudaGetSymbolAddress(&pB, g_wq);

    // 1) fp8 roundtrip -> fp16 scratch
    {
        int n4x = (int)(((long long)MM * KK) / 4);
        int n4w = (int)(((long long)NN * KK) / 4);
        quant_deq_kernel<<<(n4x + 255) / 256, 256>>>(x, (__half*)pA, n4x);
        quant_deq_kernel<<<(n4w + 255) / 256, 256>>>(W, (__half*)pB, n4w);
    }

    // 2) TMA descriptors via driver entry point (no -lcuda)
    void* fn = nullptr;
    cudaDriverEntryPointQueryResult qr;
    cudaGetDriverEntryPointByVersion("cuTensorMapEncodeTiled", &fn, 12000,
                                     cudaEnableDefault, &qr);
    if (!fn) return;
    PFN_encodeTiled encode = (PFN_encodeTiled)fn;

    CUtensorMap map_a, map_b;
    {
        cuuint64_t dims[2]    = {(cuuint64_t)KK, (cuuint64_t)MM};
        cuuint64_t strides[1] = {(cuuint64_t)KK * 2};
        cuuint32_t box[2]     = {(cuuint32_t)KC, (cuuint32_t)TILE_M};
        cuuint32_t es[2]      = {1, 1};
        if (encode(&map_a, CU_TENSOR_MAP_DATA_TYPE_FLOAT16, 2, pA, dims, strides, box, es,
                   CU_TENSOR_MAP_INTERLEAVE_NONE, CU_TENSOR_MAP_SWIZZLE_128B,
                   CU_TENSOR_MAP_L2_PROMOTION_L2_128B,
                   CU_TENSOR_MAP_FLOAT_OOB_FILL_NONE) != CUDA_SUCCESS)
            return;
    }
    {
        cuuint64_t dims[2]    = {(cuuint64_t)KK, (cuuint64_t)NN};
        cuuint64_t strides[1] = {(cuuint64_t)KK * 2};
        cuuint32_t box[2]     = {(cuuint32_t)KC, (cuuint32_t)TILE_N};
        cuuint32_t es[2]      = {1, 1};
        if (encode(&map_b, CU_TENSOR_MAP_DATA_TYPE_FLOAT16, 2, pB, dims, strides, box, es,
                   CU_TENSOR_MAP_INTERLEAVE_NONE, CU_TENSOR_MAP_SWIZZLE_128B,
                   CU_TENSOR_MAP_L2_PROMOTION_L2_128B,
                   CU_TENSOR_MAP_FLOAT_OOB_FILL_NONE) != CUDA_SUCCESS)
            return;
    }

    // 3) GEMM
    cudaFuncSetAttribute(gemm_hmma_kernel, cudaFuncAttributeMaxDynamicSharedMemorySize,
                         SMEM_BYTES);
    int grid = (MM / TILE_M) * (NN / TILE_N);   // 1024
    gemm_hmma_kernel<<<grid, 256, SMEM_BYTES>>>(map_a, map_b, bias, out);
    (void)in_sizes; (void)out_size;
}

// round 6
// speedup vs baseline: 1.9183x; 1.0172x over previous
#include <cuda_runtime.h>
#include <cuda_fp16.h>
#include <cuda_fp8.h>
#include <cuda.h>
#include <cstdint>

// ---------------------------------------------------------------------------
// Shapes (fixed): x[4,2048,4096] @ W[4096,4096]^T + bias -> out[8192,4096]
// ---------------------------------------------------------------------------
static constexpr int MM = 8192;
static constexpr int NN = 4096;
static constexpr int KK = 4096;

static constexpr int TILE_M = 128;
static constexpr int TILE_N = 256;
static constexpr int KC     = 64;          // K per stage (128B rows, SW128)
static constexpr int DEPTH  = 4;
static constexpr int ITERS  = KK / KC;     // 64

static constexpr int A_ST  = TILE_M * KC * 2;   // 16384
static constexpr int B_ST  = TILE_N * KC * 2;   // 32768
static constexpr int STAGE = A_ST + B_ST;       // 49152

static constexpr int SM_STAGE0  = 1024;         // 1024-aligned for SW128
static constexpr int SMEM_BYTES = SM_STAGE0 + DEPTH * STAGE;   // 197632

// ---------------------------------------------------------------------------
// Scratch: dequantized fp16 operands (device globals per harness rules)
// ---------------------------------------------------------------------------
__device__ __align__(1024) __half g_xq[(size_t)MM * KK];   // 64 MB
__device__ __align__(1024) __half g_wq[(size_t)NN * KK];   // 32 MB

// ---------------------------------------------------------------------------
// PTX helpers (family-portable only: TMA, mbarrier, ldmatrix, mma.sync)
// ---------------------------------------------------------------------------
__device__ __forceinline__ uint32_t smem_u32(const void* p) {
    uint32_t a;
    asm("{ .reg .u64 t; cvta.to.shared.u64 t, %1; cvt.u32.u64 %0, t; }" : "=r"(a) : "l"(p));
    return a;
}
__device__ __forceinline__ void mbar_init(uint32_t a, uint32_t cnt) {
    asm volatile("mbarrier.init.shared.b64 [%0], %1;" :: "r"(a), "r"(cnt) : "memory");
}
__device__ __forceinline__ void mbar_expect_tx(uint32_t a, uint32_t bytes) {
    asm volatile("mbarrier.arrive.expect_tx.shared.b64 _, [%0], %1;" :: "r"(a), "r"(bytes) : "memory");
}
__device__ __forceinline__ void mbar_arrive(uint32_t a) {
    asm volatile("mbarrier.arrive.shared.b64 _, [%0];" :: "r"(a) : "memory");
}
__device__ __forceinline__ void mbar_wait(uint32_t a, uint32_t ph) {
    asm volatile(
        "{\n\t.reg .pred P;\n"
        "LW_%=:\n\t"
        "mbarrier.try_wait.parity.acquire.cta.shared::cta.b64 P, [%0], %1, 0x989680;\n\t"
        "@P bra LD_%=;\n\t"
        "bra LW_%=;\n"
        "LD_%=:\n\t}"
        :: "r"(a), "r"(ph) : "memory");
}
__device__ __forceinline__ void mbar_wait_relaxed(uint32_t a, uint32_t ph) {
    asm volatile(
        "{\n\t.reg .pred P;\n"
        "LW_%=:\n\t"
        "mbarrier.try_wait.parity.relaxed.cta.shared::cta.b64 P, [%0], %1, 0x989680;\n\t"
        "@P bra LD_%=;\n\t"
        "bra LW_%=;\n"
        "LD_%=:\n\t}"
        :: "r"(a), "r"(ph) : "memory");
}
__device__ __forceinline__ void tma2d(uint32_t dst, const CUtensorMap* m, int cx, int cy, uint32_t bar) {
    asm volatile(
        "cp.async.bulk.tensor.2d.shared::cta.global.tile.mbarrier::complete_tx::bytes "
        "[%0], [%1, {%2, %3}], [%4];"
        :: "r"(dst), "l"(m), "r"(cx), "r"(cy), "r"(bar) : "memory");
}
__device__ __forceinline__ void fence_proxy_async_s() {
    asm volatile("fence.proxy.async.shared::cta;" ::: "memory");
}
__device__ __forceinline__ void ldsm_x4(uint32_t* r, uint32_t addr) {
    asm volatile("ldmatrix.sync.aligned.m8n8.x4.shared.b16 {%0,%1,%2,%3}, [%4];"
                 : "=r"(r[0]), "=r"(r[1]), "=r"(r[2]), "=r"(r[3]) : "r"(addr));
}
__device__ __forceinline__ void mma16816(float* c, const uint32_t* a, const uint32_t* b) {
    asm volatile(
        "mma.sync.aligned.m16n8k16.row.col.f32.f16.f16.f32 "
        "{%0,%1,%2,%3}, {%4,%5,%6,%7}, {%8,%9}, {%0,%1,%2,%3};"
        : "+f"(c[0]), "+f"(c[1]), "+f"(c[2]), "+f"(c[3])
        : "r"(a[0]), "r"(a[1]), "r"(a[2]), "r"(a[3]), "r"(b[0]), "r"(b[1]));
}

// ---------------------------------------------------------------------------
// Kernel 1: fp8-e4m3 group(32) pseudo-quantize -> dequantize to fp16 scratch
// thread = 8 consecutive elems (two float4 loads, one 16B store);
// group of 32 = 4 consecutive lanes (2 shfl_xor)
// ---------------------------------------------------------------------------
__device__ __forceinline__ float f8_roundtrip(float x, float scale) {
    float r = __fdiv_rn(x, scale);
    __nv_fp8_storage_t q = __nv_cvt_float_to_fp8(r, __NV_SATFINITE, __NV_E4M3);
    __half_raw hr = __nv_cvt_fp8_to_halfraw(q, __NV_E4M3);
    return __half2float(__half(hr)) * scale;
}

__global__ void __launch_bounds__(256) quant_deq_kernel(const float* __restrict__ src,
                                                        __half* __restrict__ dst, int n8) {
    int t = blockIdx.x * 256 + threadIdx.x;
    if (t >= n8) return;
    const float4* s4 = reinterpret_cast<const float4*>(src) + (size_t)t * 2;
    float4 v0 = s4[0];
    float4 v1 = s4[1];

    float amax = fmaxf(fmaxf(fabsf(v0.x), fabsf(v0.y)), fmaxf(fabsf(v0.z), fabsf(v0.w)));
    amax = fmaxf(amax, fmaxf(fmaxf(fabsf(v1.x), fabsf(v1.y)), fmaxf(fabsf(v1.z), fabsf(v1.w))));
    amax = fmaxf(amax, __shfl_xor_sync(0xffffffffu, amax, 1));
    amax = fmaxf(amax, __shfl_xor_sync(0xffffffffu, amax, 2));
    float scale = __fdiv_rn(fmaxf(amax, 1e-8f), 448.0f);

    uint4 o;
    {
        __half2 a = __halves2half2(__float2half_rn(f8_roundtrip(v0.x, scale)),
                                   __float2half_rn(f8_roundtrip(v0.y, scale)));
        __half2 b = __halves2half2(__float2half_rn(f8_roundtrip(v0.z, scale)),
                                   __float2half_rn(f8_roundtrip(v0.w, scale)));
        __half2 c = __halves2half2(__float2half_rn(f8_roundtrip(v1.x, scale)),
                                   __float2half_rn(f8_roundtrip(v1.y, scale)));
        __half2 d = __halves2half2(__float2half_rn(f8_roundtrip(v1.z, scale)),
                                   __float2half_rn(f8_roundtrip(v1.w, scale)));
        o.x = *reinterpret_cast<uint32_t*>(&a);
        o.y = *reinterpret_cast<uint32_t*>(&b);
        o.z = *reinterpret_cast<uint32_t*>(&c);
        o.w = *reinterpret_cast<uint32_t*>(&d);
    }
    reinterpret_cast<uint4*>(dst)[t] = o;
}

// ---------------------------------------------------------------------------
// Kernel 2: mma.sync fp16 GEMM  out[M,N] = A[M,K] @ B[N,K]^T + bias
// 256 threads = 8 warps, warp grid 2(M) x 4(N), warp tile 64x64
// TMA multistage (DEPTH=4) with full/empty mbarrier pairs
// ---------------------------------------------------------------------------
__global__ void __launch_bounds__(256, 1) gemm_hmma_kernel(
    const __grid_constant__ CUtensorMap tma_a,
    const __grid_constant__ CUtensorMap tma_b,
    const float* __restrict__ bias,
    float* __restrict__ out) {
    extern __shared__ char smem[];
    const uint32_t sb = smem_u32(smem);
    const int tid  = threadIdx.x;
    const int lane = tid & 31;
    const int wid  = tid >> 5;
    const int wm   = wid & 1;    // 0..1 (64-row half)
    const int wn   = wid >> 1;   // 0..3 (64-col quarter)

    // Grid swizzle: groups of 8 M-tiles, N fastest (L2 locality)
    const int TILES_N = NN / TILE_N;              // 16
    const int TIG = 8 * TILES_N;                  // 128
    int bid = blockIdx.x;
    int grp = bid / TIG, rem = bid % TIG;
    const int m0 = (grp * 8 + (rem & 7)) * TILE_M;
    const int n0 = (rem >> 3) * TILE_N;

    // barriers: full[s] @ sb+16s, empty[s] @ sb+16s+8
    if (tid == 0) {
        #pragma unroll
        for (int s = 0; s < DEPTH; s++) {
            mbar_init(sb + 16 * s, 1);       // full: expect_tx + tx
            mbar_init(sb + 16 * s + 8, 8);   // empty: one arrive per warp
        }
        fence_proxy_async_s();
    }
    __syncthreads();

    const CUtensorMap* pa = &tma_a;
    const CUtensorMap* pb = &tma_b;
    if (tid == 0) {
        asm volatile("prefetch.tensormap [%0];" :: "l"(pa));
        asm volatile("prefetch.tensormap [%0];" :: "l"(pb));
        #pragma unroll
        for (int s = 0; s < DEPTH - 1; s++) {
            mbar_expect_tx(sb + 16 * s, STAGE);
            uint32_t dst = sb + SM_STAGE0 + s * STAGE;
            tma2d(dst, pa, s * KC, m0, sb + 16 * s);
            tma2d(dst + A_ST, pb, s * KC, n0, sb + 16 * s);
        }
    }

    // ---- per-thread swizzled ldmatrix base offsets ----
    uint32_t aR[4], aSX[4];
    const uint32_t aQ = ((lane >> 4) & 1) * 16;
    #pragma unroll
    for (int mi = 0; mi < 4; mi++) {
        uint32_t row = wm * 64 + mi * 16 + (lane & 15);
        aR[mi]  = row * 128;
        aSX[mi] = (aR[mi] >> 3) & 0x70;
    }
    uint32_t bR[4], bSX[4];
    const uint32_t bQ = ((lane >> 3) & 1) * 16;
    #pragma unroll
    for (int j = 0; j < 4; j++) {
        uint32_t row = wn * 64 + j * 16 + (lane & 7) + ((lane >> 4) & 1) * 8;
        bR[j]  = row * 128;
        bSX[j] = (bR[j] >> 3) & 0x70;
    }

    float c[4][8][4];
    #pragma unroll
    for (int mi = 0; mi < 4; mi++)
        #pragma unroll
        for (int nj = 0; nj < 8; nj++)
            #pragma unroll
            for (int k = 0; k < 4; k++) c[mi][nj][k] = 0.f;

    // ---- main loop (no CTA-wide sync) ----
    for (int it = 0; it < ITERS; ++it) {
        int s = it % DEPTH;
        if (tid == 0 && it + DEPTH - 1 < ITERS) {
            int blk = it + DEPTH - 1, ss = blk % DEPTH;
            int v = blk / DEPTH;                 // reuse count of stage ss
            if (v >= 1)
                mbar_wait_relaxed(sb + 16 * ss + 8, (uint32_t)((v - 1) & 1));
            mbar_expect_tx(sb + 16 * ss, STAGE);
            uint32_t dst = sb + SM_STAGE0 + ss * STAGE;
            tma2d(dst, pa, blk * KC, m0, sb + 16 * ss);
            tma2d(dst + A_ST, pb, blk * KC, n0, sb + 16 * ss);
        }
        mbar_wait(sb + 16 * s, (uint32_t)((it / DEPTH) & 1));

        const uint32_t aS = sb + SM_STAGE0 + s * STAGE;
        const uint32_t bS = aS + A_ST;
        #pragma unroll
        for (int kk = 0; kk < KC / 16; ++kk) {
            uint32_t a[4][4], b[4][4];
            const uint32_t ck = (uint32_t)(kk * 32);
            #pragma unroll
            for (int mi = 0; mi < 4; mi++)
                ldsm_x4(a[mi], aS + aR[mi] + ((ck | aQ) ^ aSX[mi]));
            #pragma unroll
            for (int j = 0; j < 4; j++)
                ldsm_x4(b[j], bS + bR[j] + ((ck | bQ) ^ bSX[j]));
            #pragma unroll
            for (int mi = 0; mi < 4; mi++)
                #pragma unroll
                for (int nj = 0; nj < 8; nj++)
                    mma16816(c[mi][nj], a[mi], &b[nj >> 1][(nj & 1) * 2]);
        }
        if (lane == 0) mbar_arrive(sb + 16 * s + 8);
    }

    // ---- epilogue: bias + direct float2 stores ----
    const int cbase = n0 + wn * 64 + (lane & 3) * 2;
    #pragma unroll
    for (int nj = 0; nj < 8; nj++) {
        const int col = cbase + nj * 8;
        const float2 bv = *reinterpret_cast<const float2*>(&bias[col]);
        #pragma unroll
        for (int mi = 0; mi < 4; mi++) {
            const int row = m0 + wm * 64 + mi * 16 + (lane >> 2);
            float2 v0 = {c[mi][nj][0] + bv.x, c[mi][nj][1] + bv.y};
            float2 v1 = {c[mi][nj][2] + bv.x, c[mi][nj][3] + bv.y};
            *reinterpret_cast<float2*>(&out[(size_t)row * NN + col])       = v0;
            *reinterpret_cast<float2*>(&out[(size_t)(row + 8) * NN + col]) = v1;
        }
    }
}

// ---------------------------------------------------------------------------
// Host launcher
// ---------------------------------------------------------------------------
typedef CUresult (*PFN_encodeTiled)(CUtensorMap*, CUtensorMapDataType, cuuint32_t, void*,
                                    const cuuint64_t*, const cuuint64_t*, const cuuint32_t*,
                                    const cuuint32_t*, CUtensorMapInterleave, CUtensorMapSwizzle,
                                    CUtensorMapL2promotion, CUtensorMapFloatOOBfill);

extern "C" void kernel_launch(void* const* d_in, const int* in_sizes, int n_in,
                              void* d_out, int out_size) {
    if (n_in < 3) return;
    const float* x    = (const float*)d_in[0];
    const float* W    = (const float*)d_in[1];
    const float* bias = (const float*)d_in[2];
    float* out = (float*)d_out;

    void* pA = nullptr;
    void* pB = nullptr;
    cudaGetSymbolAddress(&pA, g_xq);
    cudaGetSymbolAddress(&pB, g_wq);

    // 1) fp8 roundtrip -> fp16 scratch (8 elems/thread)
    {
        int n8x = (int)(((long long)MM * KK) / 8);
        int n8w = (int)(((long long)NN * KK) / 8);
        quant_deq_kernel<<<(n8x + 255) / 256, 256>>>(x, (__half*)pA, n8x);
        quant_deq_kernel<<<(n8w + 255) / 256, 256>>>(W, (__half*)pB, n8w);
    }

    // 2) TMA descriptors via driver entry point (no -lcuda)
    void* fn = nullptr;
    cudaDriverEntryPointQueryResult qr;
    cudaGetDriverEntryPointByVersion("cuTensorMapEncodeTiled", &fn, 12000,
                                     cudaEnableDefault, &qr);
    if (!fn) return;
    PFN_encodeTiled encode = (PFN_encodeTiled)fn;

    CUtensorMap map_a, map_b;
    {
        cuuint64_t dims[2]    = {(cuuint64_t)KK, (cuuint64_t)MM};
        cuuint64_t strides[1] = {(cuuint64_t)KK * 2};
        cuuint32_t box[2]     = {(cuuint32_t)KC, (cuuint32_t)TILE_M};
        cuuint32_t es[2]      = {1, 1};
        if (encode(&map_a, CU_TENSOR_MAP_DATA_TYPE_FLOAT16, 2, pA, dims, strides, box, es,
                   CU_TENSOR_MAP_INTERLEAVE_NONE, CU_TENSOR_MAP_SWIZZLE_128B,
                   CU_TENSOR_MAP_L2_PROMOTION_L2_128B,
                   CU_TENSOR_MAP_FLOAT_OOB_FILL_NONE) != CUDA_SUCCESS)
            return;
    }
    {
        cuuint64_t dims[2]    = {(cuuint64_t)KK, (cuuint64_t)NN};
        cuuint64_t strides[1] = {(cuuint64_t)KK * 2};
        cuuint32_t box[2]     = {(cuuint32_t)KC, (cuuint32_t)TILE_N};
        cuuint32_t es[2]      = {1, 1};
        if (encode(&map_b, CU_TENSOR_MAP_DATA_TYPE_FLOAT16, 2, pB, dims, strides, box, es,
                   CU_TENSOR_MAP_INTERLEAVE_NONE, CU_TENSOR_MAP_SWIZZLE_128B,
                   CU_TENSOR_MAP_L2_PROMOTION_L2_128B,
                   CU_TENSOR_MAP_FLOAT_OOB_FILL_NONE) != CUDA_SUCCESS)
            return;
    }

    // 3) GEMM
    cudaFuncSetAttribute(gemm_hmma_kernel, cudaFuncAttributeMaxDynamicSharedMemorySize,
                         SMEM_BYTES);
    int grid = (MM / TILE_M) * (NN / TILE_N);   // 1024
    gemm_hmma_kernel<<<grid, 256, SMEM_BYTES>>>(map_a, map_b, bias, out);
    (void)in_sizes; (void)out_size;
}